// round 1
// baseline (speedup 1.0000x reference)
#include <cuda_runtime.h>

// SpikingLayer: exact-truncated-IIR EPSP filter + sequential spike/reset scan.
//
// Reference math (per row, T=1024):
//   vmem[t] = sum_{j=0}^{99} (e^{-j/10} - e^{-j/5}) * x[t-j]
//   v = vmem - r ; n = max(floor(v),0) ; r = (r+n)*alpha ; out[t] = n
// where alpha = ref_kernel[1]/ref_kernel[0] = e^{-0.1}.
//
// The K=100 FIR is computed as two truncated exponential IIRs:
//   S_i[t] = a_i*S_i[t-1] + x[t] - a_i^100 * x[t-100]
// with the lag-100 binary input served from a 128-bit per-thread ring buffer.

#define T_LEN   1024
#define CHUNK   32
#define NCHUNKS (T_LEN / CHUNK)
#define RPB     32      // rows per block == threads per block (1 warp)
#define SSTR    33      // padded shared stride (conflict-free transpose)

__global__ __launch_bounds__(RPB)
void snn_kernel(const float* __restrict__ x,
                const float* __restrict__ rk,
                float* __restrict__ out)
{
    __shared__ float tin [RPB * SSTR];
    __shared__ float tout[RPB * SSTR];

    const int tid     = threadIdx.x;
    const int rowbase = blockIdx.x * RPB;

    // alpha exactly as the reference computes it (f32 ratio of ref_kernel taps)
    const float alpha = rk[1] / rk[0];

    const float a1 = 0.90483741803595952f;    // exp(-0.1)
    const float a2 = 0.81873075307798186f;    // exp(-0.2)
    const float c1 = 4.5399929762484854e-05f; // exp(-10)  = a1^100
    const float c2 = 2.0611536224385578e-09f; // exp(-20)  = a2^100

    float s1 = 0.0f, s2 = 0.0f, r = 0.0f;
    // bit history of the binary input, one word per past 32-step chunk
    unsigned W1 = 0u, W2 = 0u, W3 = 0u, W4 = 0u;

    const int myrow = tid * SSTR;

    for (int c = 0; c < NCHUNKS; ++c) {
        const int t0 = c * CHUNK;

        // ---- load tile (coalesced float4; 4 rows x 128B per warp instruction)
        #pragma unroll
        for (int k = 0; k < 8; ++k) {
            const int f  = tid + k * 32;
            const int rr = f >> 3;
            const int jj = (f & 7) * 4;
            const float4 v = *reinterpret_cast<const float4*>(
                x + (size_t)(rowbase + rr) * T_LEN + t0 + jj);
            float* d = &tin[rr * SSTR + jj];
            d[0] = v.x; d[1] = v.y; d[2] = v.z; d[3] = v.w;
        }
        __syncwarp();

        // ---- sequential scan over this chunk (thread owns one row)
        unsigned cur = 0u;
        #pragma unroll
        for (int j = 0; j < CHUNK; ++j) {
            const float xv = tin[myrow + j];
            const unsigned b = (xv != 0.0f) ? 1u : 0u;
            cur |= (b << j);
            // x[t-100]: chunk c-4 bits 28..31 for j<4, chunk c-3 bits 0..27 else
            const unsigned lb = (j < 4) ? ((W4 >> (j + 28)) & 1u)
                                        : ((W3 >> (j - 4)) & 1u);
            s1 = fmaf(a1, s1, xv);
            s2 = fmaf(a2, s2, xv);
            if (lb) { s1 -= c1; s2 -= c2; }
            const float v = (s1 - s2) - r;
            const float n = fmaxf(floorf(v), 0.0f);
            r = (r + n) * alpha;
            tout[myrow + j] = n;
        }
        W4 = W3; W3 = W2; W2 = W1; W1 = cur;
        __syncwarp();

        // ---- store tile (coalesced float4)
        #pragma unroll
        for (int k = 0; k < 8; ++k) {
            const int f  = tid + k * 32;
            const int rr = f >> 3;
            const int jj = (f & 7) * 4;
            const float* s = &tout[rr * SSTR + jj];
            const float4 v = make_float4(s[0], s[1], s[2], s[3]);
            *reinterpret_cast<float4*>(
                out + (size_t)(rowbase + rr) * T_LEN + t0 + jj) = v;
        }
        __syncwarp();
    }
}

extern "C" void kernel_launch(void* const* d_in, const int* in_sizes, int n_in,
                              void* d_out, int out_size)
{
    const float* x  = (const float*)d_in[0];   // binary_input (1,32,1024,1024)
    // d_in[1] = epsp_kernel (folded analytically into a1/a2/c1/c2)
    const float* rk = (const float*)d_in[2];   // ref_kernel (alpha)
    float* out = (float*)d_out;                // (32,1024,1024) float32

    const int rows = out_size / T_LEN;         // 32768
    snn_kernel<<<rows / RPB, RPB>>>(x, rk, out);
    (void)in_sizes; (void)n_in;
}

// round 2
// speedup vs baseline: 1.7191x; 1.7191x over previous
#include <cuda_runtime.h>

// SpikingLayer: truncated-IIR EPSP (K=100, diff of exponentials) + spike/reset scan.
// T split into 4 segments/row with 256-step burn-in (state reconstruction);
// input bit-packed into shared so burn-in costs no extra HBM traffic.

#define T_LEN   1024
#define ROWS_PB 32
#define SEGS    4
#define SEG_CH  8          // chunks per segment (8*32 = 256 steps)
#define BSTR    33         // padded word stride per row (conflict-free)
#define THREADS 128        // 4 warps: warp w == segment w (phase 2)

__global__ __launch_bounds__(THREADS, 8)
void snn_kernel(const float* __restrict__ x,
                const float* __restrict__ rk,
                float* __restrict__ out)
{
    __shared__ unsigned sbits[ROWS_PB * BSTR];            // 4.2 KB bitmap
    __shared__ float    tstage[SEGS][ROWS_PB * BSTR];     // 16.9 KB out staging

    const int tid     = threadIdx.x;
    const int lane    = tid & 31;
    const int wid     = tid >> 5;
    const int rowbase = blockIdx.x * ROWS_PB;

    // ---------------- phase 1: load rows once, pack to bits via ballot-style shfl
    #pragma unroll
    for (int i = 0; i < 8; ++i) {
        const int row = wid * 8 + i;
        const float4* p = reinterpret_cast<const float4*>(
            x + (size_t)(rowbase + row) * T_LEN);
        #pragma unroll
        for (int b = 0; b < 8; ++b) {                     // 8 * 512B per row
            const float4 v = p[b * 32 + lane];
            unsigned nib = (unsigned)(v.x != 0.f)
                         | ((unsigned)(v.y != 0.f) << 1)
                         | ((unsigned)(v.z != 0.f) << 2)
                         | ((unsigned)(v.w != 0.f) << 3);
            unsigned val = nib << ((lane & 7) * 4);
            val |= __shfl_xor_sync(0xffffffffu, val, 1);
            val |= __shfl_xor_sync(0xffffffffu, val, 2);
            val |= __shfl_xor_sync(0xffffffffu, val, 4);
            if ((lane & 7) == 0)                          // lanes 0,8,16,24
                sbits[row * BSTR + b * 4 + (lane >> 3)] = val;
        }
    }
    __syncthreads();

    // ---------------- phase 2: per-(row,segment) scan
    const float alpha = rk[1] / rk[0];                    // e^{-0.1} as reference computes
    const float a1 = 0.90483741803595952f;                // exp(-0.1)
    const float a2 = 0.81873075307798186f;                // exp(-0.2)
    const float c1 = 4.5399929762484854e-05f;             // exp(-10) = a1^100
    const float c2 = 2.0611536224385578e-09f;             // exp(-20) = a2^100

    const int row = tid & 31;
    const int seg = wid;                                  // warp == segment
    const unsigned* __restrict__ mb = &sbits[row * BSTR];
    float* __restrict__ mo = &tstage[seg][row * BSTR];

    float s1 = 0.f, s2 = 0.f, r = 0.f;
    const int cout0 = seg * SEG_CH;
    int c = (seg == 0) ? 0 : (seg - 1) * SEG_CH;          // 256-step burn-in

    // burn-in chunks (discard output); exact lag bits come from the full-row bitmap
    for (; c < cout0; ++c) {
        const unsigned w  = mb[c];
        const unsigned wA = (c >= 4) ? mb[c - 4] : 0u;
        const unsigned wB = (c >= 3) ? mb[c - 3] : 0u;
        const unsigned lg = (wA >> 28) | (wB << 4);       // bits of x[t-100]
        #pragma unroll
        for (int j = 0; j < 32; ++j) {
            const float xf = (w >> j & 1u) ? 1.0f : 0.0f;
            s1 = fmaf(a1, s1, xf);
            s2 = fmaf(a2, s2, xf);
            if (lg >> j & 1u) { s1 -= c1; s2 -= c2; }
            const float v  = (s1 - s2) - r;
            const float n  = fmaxf(floorf(v), 0.0f);
            const float ra = r * alpha;                   // off critical path
            r = fmaf(n, alpha, ra);
        }
    }

    // output chunks: scan 32 steps into staging, then warp-cooperative coalesced store
    for (; c < cout0 + SEG_CH; ++c) {
        const unsigned w  = mb[c];
        const unsigned wA = (c >= 4) ? mb[c - 4] : 0u;
        const unsigned wB = (c >= 3) ? mb[c - 3] : 0u;
        const unsigned lg = (wA >> 28) | (wB << 4);
        #pragma unroll
        for (int j = 0; j < 32; ++j) {
            const float xf = (w >> j & 1u) ? 1.0f : 0.0f;
            s1 = fmaf(a1, s1, xf);
            s2 = fmaf(a2, s2, xf);
            if (lg >> j & 1u) { s1 -= c1; s2 -= c2; }
            const float v  = (s1 - s2) - r;
            const float n  = fmaxf(floorf(v), 0.0f);
            const float ra = r * alpha;
            r = fmaf(n, alpha, ra);
            mo[j] = n;
        }
        __syncwarp();
        #pragma unroll
        for (int k = 0; k < 8; ++k) {                     // 32 rows x 128B, coalesced
            const int f  = lane + k * 32;
            const int rr = f >> 3;
            const int jj = (f & 7) * 4;
            const float* sp = &tstage[seg][rr * BSTR + jj];
            const float4 v4 = make_float4(sp[0], sp[1], sp[2], sp[3]);
            *reinterpret_cast<float4*>(
                out + (size_t)(rowbase + rr) * T_LEN + c * 32 + jj) = v4;
        }
        __syncwarp();
    }
}

extern "C" void kernel_launch(void* const* d_in, const int* in_sizes, int n_in,
                              void* d_out, int out_size)
{
    const float* x  = (const float*)d_in[0];   // binary_input (1,32,1024,1024)
    const float* rk = (const float*)d_in[2];   // ref_kernel (alpha source)
    float* out = (float*)d_out;                // (32,1024,1024) float32

    const int rows = out_size / T_LEN;         // 32768
    snn_kernel<<<rows / ROWS_PB, THREADS>>>(x, rk, out);
    (void)in_sizes; (void)n_in;
}

// round 4
// speedup vs baseline: 1.7806x; 1.0358x over previous
#include <cuda_runtime.h>

// SpikingLayer: truncated-IIR EPSP (K=100, diff of exponentials) + spike/reset scan.
// T=1024 split into 4 balanced segments per row (14/6/6/6 output chunks; segments
// 1-3 prepend a 256-step burn-in). Both s1 and s2 carry the lag-100 correction so
// the filter state is EXACT after 100 burn-in steps (inner math identical to the
// R2 kernel that measured rel_err == 0.0).

#define T_LEN   1024
#define ROWS_PB 32
#define BSTR    33         // padded word stride per row (conflict-free)
#define THREADS 128        // 4 warps: warp w == segment w

__global__ __launch_bounds__(THREADS, 8)
void snn_kernel(const float* __restrict__ x,
                const float* __restrict__ rk,
                float* __restrict__ out)
{
    __shared__ unsigned sbits[ROWS_PB * BSTR];            // 4.2 KB input bitmap
    __shared__ float    tstage[4][ROWS_PB * BSTR];        // 16.9 KB out staging

    const int tid     = threadIdx.x;
    const int lane    = tid & 31;
    const int wid     = tid >> 5;
    const int rowbase = blockIdx.x * ROWS_PB;

    // ---------------- phase 1: load rows once (coalesced), pack to bits via shfl-OR
    #pragma unroll
    for (int i = 0; i < 8; ++i) {
        const int row = wid * 8 + i;
        const float4* p = reinterpret_cast<const float4*>(
            x + (size_t)(rowbase + row) * T_LEN);
        #pragma unroll
        for (int b = 0; b < 8; ++b) {
            const float4 v = p[b * 32 + lane];
            unsigned nib = (unsigned)(v.x != 0.f)
                         | ((unsigned)(v.y != 0.f) << 1)
                         | ((unsigned)(v.z != 0.f) << 2)
                         | ((unsigned)(v.w != 0.f) << 3);
            unsigned val = nib << ((lane & 7) * 4);
            val |= __shfl_xor_sync(0xffffffffu, val, 1);
            val |= __shfl_xor_sync(0xffffffffu, val, 2);
            val |= __shfl_xor_sync(0xffffffffu, val, 4);
            if ((lane & 7) == 0)
                sbits[row * BSTR + b * 4 + (lane >> 3)] = val;
        }
    }
    __syncthreads();

    // ---------------- phase 2: per-(row,segment) scan
    const float alpha = rk[1] / rk[0];                    // e^{-0.1} as reference computes
    const float a1 = 0.90483741803595952f;                // exp(-0.1)
    const float a2 = 0.81873075307798186f;                // exp(-0.2)
    const float c1 = 4.5399929762484854e-05f;             // exp(-10) = a1^100
    const float c2 = 2.0611536224385578e-09f;             // exp(-20) = a2^100

    // balanced output ranges (chunks of 32 steps): 14 / 6 / 6 / 6
    const int OUT0[4] = { 0, 14, 20, 26 };
    const int OUT1[4] = { 14, 20, 26, 32 };

    const int row = lane;
    const int seg = wid;
    const unsigned* __restrict__ mb = &sbits[row * BSTR];
    float* __restrict__ mo = &tstage[seg][row * BSTR];

    const int cout0 = OUT0[seg];
    const int cout1 = OUT1[seg];
    int c = (seg == 0) ? 0 : cout0 - 8;                   // 256-step burn-in

    // sliding history of bit-words (for the lag-100 term)
    unsigned h1 = (c >= 1) ? mb[c - 1] : 0u;
    unsigned h2 = (c >= 2) ? mb[c - 2] : 0u;
    unsigned h3 = (c >= 3) ? mb[c - 3] : 0u;
    unsigned h4 = (c >= 4) ? mb[c - 4] : 0u;

    float s1 = 0.f, s2 = 0.f, r = 0.f;

    // ---- burn-in chunks (discard output); state exact after 100 steps
    for (; c < cout0; ++c) {
        const unsigned w  = mb[c];
        const unsigned lg = __funnelshift_r(h4, h3, 28);  // bits of x[t-100]
        #pragma unroll
        for (int j = 0; j < 32; ++j) {
            const float xf = (w >> j & 1u) ? 1.0f : 0.0f;
            s1 = fmaf(a1, s1, xf);
            s2 = fmaf(a2, s2, xf);
            if (lg >> j & 1u) { s1 -= c1; s2 -= c2; }
            const float v = (s1 - s2) - r;
            const float n = fmaxf(floorf(v), 0.0f);
            r = fmaf(n, alpha, r * alpha);
        }
        h4 = h3; h3 = h2; h2 = h1; h1 = w;
    }

    // ---- output chunks
    for (; c < cout1; ++c) {
        const unsigned w  = mb[c];
        const unsigned lg = __funnelshift_r(h4, h3, 28);
        #pragma unroll
        for (int j = 0; j < 32; ++j) {
            const float xf = (w >> j & 1u) ? 1.0f : 0.0f;
            s1 = fmaf(a1, s1, xf);
            s2 = fmaf(a2, s2, xf);
            if (lg >> j & 1u) { s1 -= c1; s2 -= c2; }
            const float v = (s1 - s2) - r;
            const float n = fmaxf(floorf(v), 0.0f);
            r = fmaf(n, alpha, r * alpha);
            mo[j] = n;
        }
        h4 = h3; h3 = h2; h2 = h1; h1 = w;
        __syncwarp();
        #pragma unroll
        for (int k = 0; k < 8; ++k) {                     // 32 rows x 128B, coalesced
            const int f  = lane + k * 32;
            const int rr = f >> 3;
            const int jj = (f & 7) * 4;
            const float* sp = &tstage[seg][rr * BSTR + jj];
            const float4 v4 = make_float4(sp[0], sp[1], sp[2], sp[3]);
            *reinterpret_cast<float4*>(
                out + (size_t)(rowbase + rr) * T_LEN + c * 32 + jj) = v4;
        }
        __syncwarp();
    }
}

extern "C" void kernel_launch(void* const* d_in, const int* in_sizes, int n_in,
                              void* d_out, int out_size)
{
    const float* x  = (const float*)d_in[0];   // binary_input (1,32,1024,1024)
    const float* rk = (const float*)d_in[2];   // ref_kernel (alpha source)
    float* out = (float*)d_out;                // (32,1024,1024) float32

    const int rows = out_size / T_LEN;         // 32768
    snn_kernel<<<rows / ROWS_PB, THREADS>>>(x, rk, out);
    (void)in_sizes; (void)n_in;
}